// round 5
// baseline (speedup 1.0000x reference)
#include <cuda_runtime.h>
#include <cuda_bf16.h>
#include <cuda_fp8.h>
#include <cstdint>
#include <math.h>

// NT-Xent loss via e4m3 mma.sync: normalize(fp32->fp8) ->
// fused simGEMM + exp-sum epilogue -> finalize.

#define NROWS 8192
#define HALF_N 4096
#define DIM 256
#define TILE 128
#define NCOLCHUNK 4
#define COLS_PER_CHUNK 2048
#define NTILES 16           // 128-col tiles per chunk
#define ROWB 256            // bytes per tile row (256 fp8)

__device__ __align__(16) uint8_t g_zq[NROWS * DIM];   // normalized z, e4m3
__device__ float g_partial[NROWS * 8];
__device__ float g_slabel[NROWS];

__device__ __forceinline__ uint32_t smem_u32(const void* p) {
    uint32_t a;
    asm("{ .reg .u64 t; cvta.to.shared.u64 t, %1; cvt.u32.u64 %0, t; }" : "=r"(a) : "l"(p));
    return a;
}

#define CP16(dst, src) asm volatile("cp.async.cg.shared.global [%0], [%1], 16;" :: "r"(dst), "l"(src) : "memory")
#define CP_COMMIT()    asm volatile("cp.async.commit_group;" ::: "memory")
#define CP_WAIT1()     asm volatile("cp.async.wait_group 1;" ::: "memory")

__device__ __forceinline__ void ldm_x4(uint32_t* r, uint32_t addr) {
    asm volatile("ldmatrix.sync.aligned.m8n8.x4.shared.b16 {%0,%1,%2,%3}, [%4];"
                 : "=r"(r[0]), "=r"(r[1]), "=r"(r[2]), "=r"(r[3]) : "r"(addr));
}
__device__ __forceinline__ void mma_fp8(float* c, const uint32_t* a, uint32_t b0, uint32_t b1) {
    asm volatile("mma.sync.aligned.m16n8k32.row.col.f32.e4m3.e4m3.f32 "
                 "{%0,%1,%2,%3}, {%4,%5,%6,%7}, {%8,%9}, {%0,%1,%2,%3};"
                 : "+f"(c[0]), "+f"(c[1]), "+f"(c[2]), "+f"(c[3])
                 : "r"(a[0]), "r"(a[1]), "r"(a[2]), "r"(a[3]), "r"(b0), "r"(b1));
}

// Load one 128x256B fp8 tile (32KB) into smem with 16B XOR swizzle.
// 256 threads x 8 cp.async of 16B.
__device__ __forceinline__ void load_tile(uint32_t dst, int rowbase, int tid) {
    const char* base = (const char*)g_zq + (size_t)rowbase * ROWB;
    #pragma unroll
    for (int i = 0; i < 8; i++) {
        int idx = tid + 256 * i;     // 0..2047
        int r = idx >> 4;            // tile row (0..127)
        int c = idx & 15;            // 16B segment (0..15)
        uint32_t d = dst + r * ROWB + ((c ^ (r & 7)) << 4);
        CP16(d, base + (size_t)r * ROWB + c * 16);
    }
}

// ---------------- Kernel 1: normalize fp32 -> e4m3, warp per row ----------------
__global__ void normalize_kernel(const float* __restrict__ zi,
                                 const float* __restrict__ zj) {
    int wid = threadIdx.x >> 5, lane = threadIdx.x & 31;
    int row = blockIdx.x * 8 + wid;
    const float* src = (row < HALF_N) ? (zi + (size_t)row * DIM)
                                      : (zj + (size_t)(row - HALF_N) * DIM);
    const float4* s4 = (const float4*)src;
    float4 a = s4[lane * 2];
    float4 b = s4[lane * 2 + 1];
    float ss = a.x*a.x + a.y*a.y + a.z*a.z + a.w*a.w
             + b.x*b.x + b.y*b.y + b.z*b.z + b.w*b.w;
    #pragma unroll
    for (int o = 16; o > 0; o >>= 1) ss += __shfl_xor_sync(0xffffffffu, ss, o);
    float inv = rsqrtf(fmaxf(ss, 1e-16f));
    unsigned short q0 = __nv_cvt_float2_to_fp8x2(make_float2(a.x*inv, a.y*inv), __NV_SATFINITE, __NV_E4M3);
    unsigned short q1 = __nv_cvt_float2_to_fp8x2(make_float2(a.z*inv, a.w*inv), __NV_SATFINITE, __NV_E4M3);
    unsigned short q2 = __nv_cvt_float2_to_fp8x2(make_float2(b.x*inv, b.y*inv), __NV_SATFINITE, __NV_E4M3);
    unsigned short q3 = __nv_cvt_float2_to_fp8x2(make_float2(b.z*inv, b.w*inv), __NV_SATFINITE, __NV_E4M3);
    uint2 out;
    out.x = (uint32_t)q0 | ((uint32_t)q1 << 16);
    out.y = (uint32_t)q2 | ((uint32_t)q3 << 16);
    *(uint2*)(g_zq + (size_t)row * ROWB + lane * 8) = out;
}

// ---------------- Kernel 2: fused sim GEMM (mma.sync fp8) + exp-sum ------------
// Grid (4, 64). 256 threads = 8 warps: warp_m = wid&3 (32 rows), warp_n = wid>>2
// (64 cols). Warp tile 32x64, frag m16n8k32 e4m3.
// Smem: A (32KB, full K=256) + B double buffer (2 x 32KB) = 96KB -> occ 2.
__global__ __launch_bounds__(256, 2) void simloss_kernel() {
    extern __shared__ char smem[];
    const uint32_t sb = smem_u32(smem);
    const uint32_t A_OFF = sb;
    const uint32_t B_OFF[2] = { sb + 32768, sb + 65536 };

    const int tid = threadIdx.x, wid = tid >> 5, lane = tid & 31;
    const int wm = wid & 3, wn = wid >> 2;
    const int cc = blockIdx.x;
    const int rbase = blockIdx.y * TILE;

    // Preload A and first two B tiles.
    load_tile(A_OFF, rbase, tid);
    load_tile(B_OFF[0], cc * COLS_PER_CHUNK, tid);
    CP_COMMIT();                                    // group: {A, B0}
    load_tile(B_OFF[1], cc * COLS_PER_CHUNK + TILE, tid);
    CP_COMMIT();                                    // group: {B1}

    // ldmatrix per-lane row bases (constant over k-steps).
    const int h = lane >> 4;                        // 16B-segment half select
    uint32_t a_row[2], a_x[2];
    #pragma unroll
    for (int m = 0; m < 2; m++) {
        int r = wm * 32 + m * 16 + (lane & 15);
        a_row[m] = A_OFF + r * ROWB;
        a_x[m] = r & 7;
    }
    uint32_t b_row[4], b_x[4];
    #pragma unroll
    for (int n = 0; n < 4; n++) {
        int r = wn * 64 + n * 16 + (lane & 15);
        b_row[n] = r * ROWB;
        b_x[n] = r & 7;
    }

    // Per-thread global rows for the 4 accum row positions [m][rhalf].
    int growr[2][2];
    #pragma unroll
    for (int m = 0; m < 2; m++)
        #pragma unroll
        for (int rh = 0; rh < 2; rh++)
            growr[m][rh] = rbase + wm * 32 + m * 16 + (lane >> 2) + rh * 8;

    float sum[2][2] = {{0.f, 0.f}, {0.f, 0.f}};
    float slab[2][2] = {{0.f, 0.f}, {0.f, 0.f}};

    for (int t = 0; t < NTILES; t++) {
        const uint32_t bb = B_OFF[t & 1];
        CP_WAIT1();                 // tile t resident (t+1 still in flight)
        __syncthreads();

        float acc[2][8][4];
        #pragma unroll
        for (int m = 0; m < 2; m++)
            #pragma unroll
            for (int n = 0; n < 8; n++)
                #pragma unroll
                for (int k = 0; k < 4; k++) acc[m][n][k] = 0.f;

        #pragma unroll
        for (int ks = 0; ks < 8; ks++) {            // k32 per step, K=256
            const uint32_t c = 2 * ks + h;
            uint32_t ar[2][4], br[4][4];
            #pragma unroll
            for (int m = 0; m < 2; m++)
                ldm_x4(ar[m], a_row[m] + ((c ^ a_x[m]) << 4));
            #pragma unroll
            for (int n = 0; n < 4; n++)
                ldm_x4(br[n], bb + b_row[n] + ((c ^ b_x[n]) << 4));
            #pragma unroll
            for (int m = 0; m < 2; m++)
                #pragma unroll
                for (int n = 0; n < 4; n++) {
                    mma_fp8(acc[m][2 * n],     ar[m], br[n][0], br[n][2]);
                    mma_fp8(acc[m][2 * n + 1], ar[m], br[n][1], br[n][3]);
                }
        }

        __syncthreads();            // everyone done reading B[t&1]
        if (t + 2 < NTILES) {
            load_tile(B_OFF[t & 1], cc * COLS_PER_CHUNK + (t + 2) * TILE, tid);
        }
        CP_COMMIT();                // keep group count uniform

        // Epilogue on registers (overlaps in-flight cp.async + peer CTA's mma).
        const int cbase = cc * COLS_PER_CHUNK + t * TILE + wn * 64 + (lane & 3) * 2;
        #pragma unroll
        for (int m = 0; m < 2; m++)
            #pragma unroll
            for (int n = 0; n < 8; n++)
                #pragma unroll
                for (int k = 0; k < 4; k++) {
                    const int rh = k >> 1;
                    const int grow = growr[m][rh];
                    const int gcol = cbase + n * 8 + (k & 1);
                    float s = 2.0f * acc[m][n][k];      // / temperature
                    float e = __expf(s);
                    if (gcol != grow) sum[m][rh] += e;  // mask diagonal
                    if (gcol == (grow ^ HALF_N)) slab[m][rh] = s;
                }
    }

    // Reduce across the 4 lanes sharing each row (lane&3 varies).
    #pragma unroll
    for (int m = 0; m < 2; m++)
        #pragma unroll
        for (int rh = 0; rh < 2; rh++) {
            #pragma unroll
            for (int o = 1; o < 4; o <<= 1) {
                sum[m][rh]  += __shfl_xor_sync(0xffffffffu, sum[m][rh], o);
                slab[m][rh] += __shfl_xor_sync(0xffffffffu, slab[m][rh], o);
            }
        }
    if ((lane & 3) == 0) {
        #pragma unroll
        for (int m = 0; m < 2; m++)
            #pragma unroll
            for (int rh = 0; rh < 2; rh++) {
                const int grow = growr[m][rh];
                g_partial[grow * 8 + cc * 2 + wn] = sum[m][rh];
                const int lb = grow ^ HALF_N;   // label column
                if ((lb >> 11) == cc && (((lb >> 6) & 1) == wn))
                    g_slabel[grow] = slab[m][rh];
            }
    }
}

// ---------------- Kernel 3: deterministic final reduction ----------------
__global__ void finalize_kernel(float* __restrict__ out) {
    int tid = threadIdx.x;   // 256
    float local = 0.f;
    for (int row = tid; row < NROWS; row += 256) {
        const float4* p = (const float4*)&g_partial[row * 8];
        float4 x = p[0], y = p[1];
        float s = (x.x + x.y + x.z + x.w) + (y.x + y.y + y.z + y.w);
        local += logf(s) - g_slabel[row];
    }
    #pragma unroll
    for (int o = 16; o > 0; o >>= 1) local += __shfl_xor_sync(0xffffffffu, local, o);
    __shared__ float ws[8];
    if ((tid & 31) == 0) ws[tid >> 5] = local;
    __syncthreads();
    if (tid == 0) {
        float tot = 0.f;
        #pragma unroll
        for (int i = 0; i < 8; i++) tot += ws[i];
        out[0] = tot / (float)NROWS;
    }
}

extern "C" void kernel_launch(void* const* d_in, const int* in_sizes, int n_in,
                              void* d_out, int out_size) {
    const float* zi = (const float*)d_in[0];
    const float* zj = (const float*)d_in[1];
    float* out = (float*)d_out;

    cudaFuncSetAttribute(simloss_kernel,
                         cudaFuncAttributeMaxDynamicSharedMemorySize, 98304);

    normalize_kernel<<<NROWS / 8, 256>>>(zi, zj);
    dim3 grid(NCOLCHUNK, NROWS / TILE);
    simloss_kernel<<<grid, 256, 98304>>>();
    finalize_kernel<<<1, 256>>>(out);
}

// round 6
// speedup vs baseline: 1.7546x; 1.7546x over previous
#include <cuda_runtime.h>
#include <cuda_bf16.h>
#include <cuda_fp8.h>
#include <cstdint>
#include <math.h>

// NT-Xent loss, symmetric-triangle fp8 mma.sync version.
// sim is symmetric: compute only upper-triangle 128x128 tiles (2080 of 4096),
// each tile contributes exp-sums to its rows AND its columns.

#define NROWS 8192
#define HALF_N 4096
#define DIM 256
#define TILE 128
#define NTILE 64            // 64x64 tile grid
#define TRI_CTAS 416        // 2080 tiles / 5 per CTA
#define TPC 5               // tiles per CTA (65 = 13*5 per pair block)
#define ROWB 256            // bytes per tile row (256 fp8)
#define NSLOT 128           // partial slots per row

__device__ __align__(16) uint8_t g_zq[NROWS * DIM];   // normalized z, e4m3
__device__ float g_partial[(size_t)NROWS * NSLOT];
__device__ float g_slabel[NROWS];
__device__ float g_bsum[256];

__device__ __forceinline__ uint32_t smem_u32(const void* p) {
    uint32_t a;
    asm("{ .reg .u64 t; cvta.to.shared.u64 t, %1; cvt.u32.u64 %0, t; }" : "=r"(a) : "l"(p));
    return a;
}

#define CP16(dst, src) asm volatile("cp.async.cg.shared.global [%0], [%1], 16;" :: "r"(dst), "l"(src) : "memory")
#define CP_COMMIT()    asm volatile("cp.async.commit_group;" ::: "memory")
#define CP_WAIT1()     asm volatile("cp.async.wait_group 1;" ::: "memory")
#define CP_WAIT0()     asm volatile("cp.async.wait_group 0;" ::: "memory")

__device__ __forceinline__ void ldm_x4(uint32_t* r, uint32_t addr) {
    asm volatile("ldmatrix.sync.aligned.m8n8.x4.shared.b16 {%0,%1,%2,%3}, [%4];"
                 : "=r"(r[0]), "=r"(r[1]), "=r"(r[2]), "=r"(r[3]) : "r"(addr));
}
__device__ __forceinline__ void mma_fp8(float* c, const uint32_t* a, uint32_t b0, uint32_t b1) {
    asm volatile("mma.sync.aligned.m16n8k32.row.col.f32.e4m3.e4m3.f32 "
                 "{%0,%1,%2,%3}, {%4,%5,%6,%7}, {%8,%9}, {%0,%1,%2,%3};"
                 : "+f"(c[0]), "+f"(c[1]), "+f"(c[2]), "+f"(c[3])
                 : "r"(a[0]), "r"(a[1]), "r"(a[2]), "r"(a[3]), "r"(b0), "r"(b1));
}

// Upper-triangle tile enumeration via row-pair balancing:
// pair p handles rows {p, 63-p} -> exactly 65 tiles; t in [65p, 65p+65).
__device__ __forceinline__ void tile_ij(int t, int& i, int& j) {
    int p = t / 65;
    int q = t - p * 65;
    if (q < 64 - p) { i = p; j = p + q; }
    else            { i = 63 - p; j = q - 1; }
}

// Load one 128x256B fp8 tile (32KB) into smem with 16B XOR swizzle.
__device__ __forceinline__ void load_tile(uint32_t dst, int tile, int tid) {
    const char* base = (const char*)g_zq + (size_t)tile * TILE * ROWB;
    #pragma unroll
    for (int i = 0; i < 8; i++) {
        int idx = tid + 256 * i;     // 0..2047
        int r = idx >> 4;            // tile row
        int c = idx & 15;            // 16B segment
        uint32_t d = dst + r * ROWB + ((c ^ (r & 7)) << 4);
        CP16(d, base + (size_t)r * ROWB + c * 16);
    }
}

// ---------------- Kernel 1: normalize fp32 -> e4m3, warp per row ----------------
__global__ void normalize_kernel(const float* __restrict__ zi,
                                 const float* __restrict__ zj) {
    int wid = threadIdx.x >> 5, lane = threadIdx.x & 31;
    int row = blockIdx.x * 8 + wid;
    const float* src = (row < HALF_N) ? (zi + (size_t)row * DIM)
                                      : (zj + (size_t)(row - HALF_N) * DIM);
    const float4* s4 = (const float4*)src;
    float4 a = s4[lane * 2];
    float4 b = s4[lane * 2 + 1];
    float ss = a.x*a.x + a.y*a.y + a.z*a.z + a.w*a.w
             + b.x*b.x + b.y*b.y + b.z*b.z + b.w*b.w;
    #pragma unroll
    for (int o = 16; o > 0; o >>= 1) ss += __shfl_xor_sync(0xffffffffu, ss, o);
    float inv = rsqrtf(fmaxf(ss, 1e-16f));
    unsigned short q0 = __nv_cvt_float2_to_fp8x2(make_float2(a.x*inv, a.y*inv), __NV_SATFINITE, __NV_E4M3);
    unsigned short q1 = __nv_cvt_float2_to_fp8x2(make_float2(a.z*inv, a.w*inv), __NV_SATFINITE, __NV_E4M3);
    unsigned short q2 = __nv_cvt_float2_to_fp8x2(make_float2(b.x*inv, b.y*inv), __NV_SATFINITE, __NV_E4M3);
    unsigned short q3 = __nv_cvt_float2_to_fp8x2(make_float2(b.z*inv, b.w*inv), __NV_SATFINITE, __NV_E4M3);
    uint2 out;
    out.x = (uint32_t)q0 | ((uint32_t)q1 << 16);
    out.y = (uint32_t)q2 | ((uint32_t)q3 << 16);
    *(uint2*)(g_zq + (size_t)row * ROWB + lane * 8) = out;
}

// ---------------- Kernel 2: triangle sim GEMM + dual exp-sum epilogue ----------
// 416 CTAs x 5 tiles. 256 threads = 8 warps (wm = wid&3 rows, wn = wid>>2 cols).
// Smem: A (32KB) + B double buffer (2x32KB) = 96KB dynamic -> occupancy 2.
__global__ __launch_bounds__(256, 2) void simloss_kernel() {
    extern __shared__ char smem[];
    __shared__ float colstage[4][128];
    const uint32_t sb = smem_u32(smem);
    const uint32_t A_OFF = sb;
    const uint32_t B_OFF[2] = { sb + 32768, sb + 65536 };

    const int tid = threadIdx.x, wid = tid >> 5, lane = tid & 31;
    const int wm = wid & 3, wn = wid >> 2;
    const int t0 = blockIdx.x * TPC;

    // Prologue: tiles t0, t0+1.
    int i0, j0, i1x, j1x;
    tile_ij(t0, i0, j0);
    tile_ij(t0 + 1, i1x, j1x);
    load_tile(A_OFF, i0, tid);
    load_tile(B_OFF[0], j0, tid);
    CP_COMMIT();                       // P1: {A(i0), B(j0)}
    load_tile(B_OFF[1], j1x, tid);
    CP_COMMIT();                       // P2: {B(j1)}

    // ldmatrix per-lane row bases.
    const int h = lane >> 4;
    uint32_t a_row[2], a_x[2];
    #pragma unroll
    for (int m = 0; m < 2; m++) {
        int r = wm * 32 + m * 16 + (lane & 15);
        a_row[m] = A_OFF + r * ROWB;
        a_x[m] = r & 7;
    }
    uint32_t b_row[4], b_x[4];
    #pragma unroll
    for (int n = 0; n < 4; n++) {
        int r = wn * 64 + n * 16 + (lane & 15);
        b_row[n] = r * ROWB;
        b_x[n] = r & 7;
    }

    const int lr = lane >> 2;          // 0..7
    const int c4 = lane & 3;

    int iprev = i0;
    for (int k = 0; k < TPC; k++) {
        int ii, jj;
        tile_ij(t0 + k, ii, jj);
        const bool achg = (k > 0) && (ii != iprev);
        iprev = ii;

        if (achg) CP_WAIT0(); else CP_WAIT1();
        __syncthreads();

        // ---- MMA 128x128x256 (e4m3) ----
        const uint32_t bb = B_OFF[k & 1];
        float acc[2][8][4];
        #pragma unroll
        for (int m = 0; m < 2; m++)
            #pragma unroll
            for (int n = 0; n < 8; n++)
                #pragma unroll
                for (int q = 0; q < 4; q++) acc[m][n][q] = 0.f;

        #pragma unroll
        for (int ks = 0; ks < 8; ks++) {
            const uint32_t c = 2 * ks + h;
            uint32_t ar[2][4], br[4][4];
            #pragma unroll
            for (int m = 0; m < 2; m++)
                ldm_x4(ar[m], a_row[m] + ((c ^ a_x[m]) << 4));
            #pragma unroll
            for (int n = 0; n < 4; n++)
                ldm_x4(br[n], bb + b_row[n] + ((c ^ b_x[n]) << 4));
            #pragma unroll
            for (int m = 0; m < 2; m++)
                #pragma unroll
                for (int n = 0; n < 4; n++) {
                    mma_fp8(acc[m][2 * n],     ar[m], br[n][0], br[n][2]);
                    mma_fp8(acc[m][2 * n + 1], ar[m], br[n][1], br[n][3]);
                }
        }

        __syncthreads();               // done reading smem tiles

        // Prefetch: A for tile k+1 if row-tile changes; B for tile k+2.
        if (k + 1 < TPC) {
            int in, jn;
            tile_ij(t0 + k + 1, in, jn);
            if (in != ii) load_tile(A_OFF, in, tid);
        }
        if (k + 2 < TPC) {
            int in2, jn2;
            tile_ij(t0 + k + 2, in2, jn2);
            load_tile(B_OFF[k & 1], jn2, tid);
        }
        CP_COMMIT();

        // ---- Epilogue: row sums + column sums + label capture ----
        const bool isdiag = (ii == jj);
        const bool islab = ((ii ^ jj) == 32);
        float rs[2][2] = {{0.f, 0.f}, {0.f, 0.f}};
        float cs[8][2];
        #pragma unroll
        for (int n = 0; n < 8; n++) { cs[n][0] = 0.f; cs[n][1] = 0.f; }

        #pragma unroll
        for (int m = 0; m < 2; m++)
            #pragma unroll
            for (int n = 0; n < 8; n++)
                #pragma unroll
                for (int q = 0; q < 4; q++) {
                    const int rh = q >> 1, kp = q & 1;
                    const int rloc = wm * 32 + m * 16 + lr + rh * 8;
                    const int cloc = wn * 64 + n * 8 + c4 * 2 + kp;
                    float s = 2.0f * acc[m][n][q];
                    float e = __expf(s);
                    bool dg = isdiag && (rloc == cloc);
                    if (!dg) { rs[m][rh] += e; cs[n][kp] += e; }
                    if (islab && rloc == cloc) {
                        g_slabel[TILE * ii + rloc] = s;
                        g_slabel[TILE * jj + cloc] = s;
                    }
                }

        // Row reduce over lanes differing in bits 0-1 (cols).
        #pragma unroll
        for (int m = 0; m < 2; m++)
            #pragma unroll
            for (int rh = 0; rh < 2; rh++) {
                rs[m][rh] += __shfl_xor_sync(0xffffffffu, rs[m][rh], 1);
                rs[m][rh] += __shfl_xor_sync(0xffffffffu, rs[m][rh], 2);
            }
        if (c4 == 0) {
            #pragma unroll
            for (int m = 0; m < 2; m++)
                #pragma unroll
                for (int rh = 0; rh < 2; rh++) {
                    int grow = TILE * ii + wm * 32 + m * 16 + lr + rh * 8;
                    g_partial[(size_t)grow * NSLOT + 2 * jj + wn] = rs[m][rh];
                }
        }

        // Column reduce over lanes differing in bits 2-4 (rows), then wm via smem.
        #pragma unroll
        for (int n = 0; n < 8; n++)
            #pragma unroll
            for (int kp = 0; kp < 2; kp++) {
                cs[n][kp] += __shfl_xor_sync(0xffffffffu, cs[n][kp], 4);
                cs[n][kp] += __shfl_xor_sync(0xffffffffu, cs[n][kp], 8);
                cs[n][kp] += __shfl_xor_sync(0xffffffffu, cs[n][kp], 16);
            }
        if (lane < 4) {
            #pragma unroll
            for (int n = 0; n < 8; n++)
                #pragma unroll
                for (int kp = 0; kp < 2; kp++)
                    colstage[wm][wn * 64 + n * 8 + lane * 2 + kp] = cs[n][kp];
        }
        __syncthreads();
        if (!isdiag && tid < 128) {
            float v = colstage[0][tid] + colstage[1][tid]
                    + colstage[2][tid] + colstage[3][tid];
            size_t base = (size_t)(TILE * jj + tid) * NSLOT;
            g_partial[base + 2 * ii] = v;
            g_partial[base + 2 * ii + 1] = 0.f;   // sibling slot unused by col side
        }
    }
}

// ---------------- Kernel 3a: per-row logsumexp-label, 256 blocks ----------------
__global__ void finalize1_kernel() {
    const int tid = threadIdx.x, lane = tid & 31;
    const int row = blockIdx.x * 32 + (tid >> 3);
    const float4* p = (const float4*)&g_partial[(size_t)row * NSLOT + (tid & 7) * 16];
    float4 a = p[0], b = p[1], c = p[2], d = p[3];
    float s = (a.x + a.y + a.z + a.w) + (b.x + b.y + b.z + b.w)
            + (c.x + c.y + c.z + c.w) + (d.x + d.y + d.z + d.w);
    s += __shfl_xor_sync(0xffffffffu, s, 1);
    s += __shfl_xor_sync(0xffffffffu, s, 2);
    s += __shfl_xor_sync(0xffffffffu, s, 4);
    float val = ((tid & 7) == 0) ? (logf(s) - g_slabel[row]) : 0.f;
    val += __shfl_xor_sync(0xffffffffu, val, 8);
    val += __shfl_xor_sync(0xffffffffu, val, 16);
    __shared__ float ws[8];
    if (lane == 0) ws[tid >> 5] = val;
    __syncthreads();
    if (tid == 0) {
        float t = 0.f;
        #pragma unroll
        for (int i = 0; i < 8; i++) t += ws[i];
        g_bsum[blockIdx.x] = t;
    }
}

// ---------------- Kernel 3b: final scalar ----------------
__global__ void finalize2_kernel(float* __restrict__ out) {
    const int tid = threadIdx.x;   // 256
    float v = g_bsum[tid];
    #pragma unroll
    for (int o = 16; o > 0; o >>= 1) v += __shfl_xor_sync(0xffffffffu, v, o);
    __shared__ float ws[8];
    if ((tid & 31) == 0) ws[tid >> 5] = v;
    __syncthreads();
    if (tid == 0) {
        float t = 0.f;
        #pragma unroll
        for (int i = 0; i < 8; i++) t += ws[i];
        out[0] = t / (float)NROWS;
    }
}

extern "C" void kernel_launch(void* const* d_in, const int* in_sizes, int n_in,
                              void* d_out, int out_size) {
    const float* zi = (const float*)d_in[0];
    const float* zj = (const float*)d_in[1];
    float* out = (float*)d_out;

    cudaFuncSetAttribute(simloss_kernel,
                         cudaFuncAttributeMaxDynamicSharedMemorySize, 98304);

    normalize_kernel<<<NROWS / 8, 256>>>(zi, zj);
    simloss_kernel<<<TRI_CTAS, 256, 98304>>>();
    finalize1_kernel<<<256, 256>>>();
    finalize2_kernel<<<1, 256>>>(out);
}

// round 7
// speedup vs baseline: 1.9084x; 1.0877x over previous
#include <cuda_runtime.h>
#include <cuda_bf16.h>
#include <cuda_fp8.h>
#include <cstdint>
#include <math.h>

// NT-Xent loss, symmetric-triangle fp8 mma.sync, single-wave schedule.

#define NROWS 8192
#define HALF_N 4096
#define DIM 256
#define TILE 128
#define NTILE 64            // 64x64 tile grid
#define NTRI 2080           // upper-triangle tiles
#define GEMM_CTAS 296       // = 148 SMs x occ 2, single wave
#define ROWB 256            // bytes per tile row (256 fp8)
#define NSLOT 128           // partial slots per row
#define SCALE_EX2 2.8853900817779268f   // 2 / ln(2)  (exp(2x) = 2^(x*SCALE))

__device__ __align__(16) uint8_t g_zq[NROWS * DIM];
__device__ float g_partial[(size_t)NROWS * NSLOT];
__device__ float g_slabel[NROWS];
__device__ float g_bsum[256];
__device__ unsigned g_ticket = 0;

__device__ __forceinline__ uint32_t smem_u32(const void* p) {
    uint32_t a;
    asm("{ .reg .u64 t; cvta.to.shared.u64 t, %1; cvt.u32.u64 %0, t; }" : "=r"(a) : "l"(p));
    return a;
}
__device__ __forceinline__ float ex2f(float x) {
    float r;
    asm("ex2.approx.f32 %0, %1;" : "=f"(r) : "f"(x));
    return r;
}

#define CP16(dst, src) asm volatile("cp.async.cg.shared.global [%0], [%1], 16;" :: "r"(dst), "l"(src) : "memory")
#define CP_COMMIT()    asm volatile("cp.async.commit_group;" ::: "memory")
#define CP_WAIT1()     asm volatile("cp.async.wait_group 1;" ::: "memory")
#define CP_WAIT0()     asm volatile("cp.async.wait_group 0;" ::: "memory")

__device__ __forceinline__ void ldm_x4(uint32_t* r, uint32_t addr) {
    asm volatile("ldmatrix.sync.aligned.m8n8.x4.shared.b16 {%0,%1,%2,%3}, [%4];"
                 : "=r"(r[0]), "=r"(r[1]), "=r"(r[2]), "=r"(r[3]) : "r"(addr));
}
__device__ __forceinline__ void mma_fp8(float* c, const uint32_t* a, uint32_t b0, uint32_t b1) {
    asm volatile("mma.sync.aligned.m16n8k32.row.col.f32.e4m3.e4m3.f32 "
                 "{%0,%1,%2,%3}, {%4,%5,%6,%7}, {%8,%9}, {%0,%1,%2,%3};"
                 : "+f"(c[0]), "+f"(c[1]), "+f"(c[2]), "+f"(c[3])
                 : "r"(a[0]), "r"(a[1]), "r"(a[2]), "r"(a[3]), "r"(b0), "r"(b1));
}

// Upper-triangle tile enumeration, pair-balanced: pair p = rows {p, 63-p},
// 65 tiles each; t in [65p, 65p+65).
__device__ __forceinline__ void tile_ij(int t, int& i, int& j) {
    int p = t / 65;
    int q = t - p * 65;
    if (q < 64 - p) { i = p; j = p + q; }
    else            { i = 63 - p; j = q - 1; }
}

// Load one 128x256B fp8 tile (32KB) into smem with 16B XOR swizzle.
__device__ __forceinline__ void load_tile(uint32_t dst, int tile, int tid) {
    const char* base = (const char*)g_zq + (size_t)tile * TILE * ROWB;
    #pragma unroll
    for (int i = 0; i < 8; i++) {
        int idx = tid + 256 * i;
        int r = idx >> 4;
        int c = idx & 15;
        uint32_t d = dst + r * ROWB + ((c ^ (r & 7)) << 4);
        CP16(d, base + (size_t)r * ROWB + c * 16);
    }
}

// ---------------- Kernel 1: normalize fp32 -> e4m3, 4 rows per warp ------------
__global__ void normalize_kernel(const float* __restrict__ zi,
                                 const float* __restrict__ zj) {
    const int wid = threadIdx.x >> 5, lane = threadIdx.x & 31;
    const int row0 = blockIdx.x * 32 + wid * 4;

    float4 v[4][2];
    #pragma unroll
    for (int r = 0; r < 4; r++) {
        int row = row0 + r;
        const float* src = (row < HALF_N) ? (zi + (size_t)row * DIM)
                                          : (zj + (size_t)(row - HALF_N) * DIM);
        const float4* s4 = (const float4*)src;
        v[r][0] = s4[lane * 2];
        v[r][1] = s4[lane * 2 + 1];
    }
    #pragma unroll
    for (int r = 0; r < 4; r++) {
        float4 a = v[r][0], b = v[r][1];
        float ss = a.x*a.x + a.y*a.y + a.z*a.z + a.w*a.w
                 + b.x*b.x + b.y*b.y + b.z*b.z + b.w*b.w;
        #pragma unroll
        for (int o = 16; o > 0; o >>= 1) ss += __shfl_xor_sync(0xffffffffu, ss, o);
        float inv = rsqrtf(fmaxf(ss, 1e-16f));
        unsigned short q0 = __nv_cvt_float2_to_fp8x2(make_float2(a.x*inv, a.y*inv), __NV_SATFINITE, __NV_E4M3);
        unsigned short q1 = __nv_cvt_float2_to_fp8x2(make_float2(a.z*inv, a.w*inv), __NV_SATFINITE, __NV_E4M3);
        unsigned short q2 = __nv_cvt_float2_to_fp8x2(make_float2(b.x*inv, b.y*inv), __NV_SATFINITE, __NV_E4M3);
        unsigned short q3 = __nv_cvt_float2_to_fp8x2(make_float2(b.z*inv, b.w*inv), __NV_SATFINITE, __NV_E4M3);
        uint2 out;
        out.x = (uint32_t)q0 | ((uint32_t)q1 << 16);
        out.y = (uint32_t)q2 | ((uint32_t)q3 << 16);
        *(uint2*)(g_zq + (size_t)(row0 + r) * ROWB + lane * 8) = out;
    }
}

// ---------------- Kernel 2: triangle sim GEMM + dual exp-sum epilogue ----------
// 296 CTAs, 7 tiles each (+1 for first 8 CTAs). Single wave at occupancy 2.
__global__ __launch_bounds__(256, 2) void simloss_kernel() {
    extern __shared__ char smem[];
    __shared__ float colstage[4][128];
    const uint32_t sb = smem_u32(smem);
    const uint32_t A_OFF = sb;
    const uint32_t B_OFF[2] = { sb + 32768, sb + 65536 };

    const int tid = threadIdx.x, wid = tid >> 5, lane = tid & 31;
    const int wm = wid & 3, wn = wid >> 2;
    const int b = blockIdx.x;
    const int t0 = b * 7 + min(b, 8);
    const int cnt = 7 + (b < 8 ? 1 : 0);

    int i0, j0, i1x, j1x;
    tile_ij(t0, i0, j0);
    tile_ij(t0 + 1, i1x, j1x);
    load_tile(A_OFF, i0, tid);
    load_tile(B_OFF[0], j0, tid);
    CP_COMMIT();
    load_tile(B_OFF[1], j1x, tid);
    CP_COMMIT();

    const int h = lane >> 4;
    uint32_t a_row[2], a_x[2];
    #pragma unroll
    for (int m = 0; m < 2; m++) {
        int r = wm * 32 + m * 16 + (lane & 15);
        a_row[m] = A_OFF + r * ROWB;
        a_x[m] = r & 7;
    }
    uint32_t b_row[4], b_x[4];
    #pragma unroll
    for (int n = 0; n < 4; n++) {
        int r = wn * 64 + n * 16 + (lane & 15);
        b_row[n] = r * ROWB;
        b_x[n] = r & 7;
    }

    const int lr = lane >> 2;
    const int c4 = lane & 3;

    int iprev = i0;
    for (int k = 0; k < cnt; k++) {
        int ii, jj;
        tile_ij(t0 + k, ii, jj);
        const bool achg = (k > 0) && (ii != iprev);
        iprev = ii;

        if (achg) CP_WAIT0(); else CP_WAIT1();
        __syncthreads();

        // ---- MMA 128x128x256 e4m3 ----
        const uint32_t bb = B_OFF[k & 1];
        float acc[2][8][4];
        #pragma unroll
        for (int m = 0; m < 2; m++)
            #pragma unroll
            for (int n = 0; n < 8; n++)
                #pragma unroll
                for (int q = 0; q < 4; q++) acc[m][n][q] = 0.f;

        #pragma unroll
        for (int ks = 0; ks < 8; ks++) {
            const uint32_t c = 2 * ks + h;
            uint32_t ar[2][4], br[4][4];
            #pragma unroll
            for (int m = 0; m < 2; m++)
                ldm_x4(ar[m], a_row[m] + ((c ^ a_x[m]) << 4));
            #pragma unroll
            for (int n = 0; n < 4; n++)
                ldm_x4(br[n], bb + b_row[n] + ((c ^ b_x[n]) << 4));
            #pragma unroll
            for (int m = 0; m < 2; m++)
                #pragma unroll
                for (int n = 0; n < 4; n++) {
                    mma_fp8(acc[m][2 * n],     ar[m], br[n][0], br[n][2]);
                    mma_fp8(acc[m][2 * n + 1], ar[m], br[n][1], br[n][3]);
                }
        }

        __syncthreads();

        // Prefetch A (if row-tile changes) and B (k+2).
        if (k + 1 < cnt) {
            int in, jn;
            tile_ij(t0 + k + 1, in, jn);
            if (in != ii) load_tile(A_OFF, in, tid);
        }
        if (k + 2 < cnt) {
            int in2, jn2;
            tile_ij(t0 + k + 2, in2, jn2);
            load_tile(B_OFF[k & 1], jn2, tid);
        }
        CP_COMMIT();

        // ---- Epilogue ----
        const bool isdiag = (ii == jj);
        const bool islab = ((ii ^ jj) == 32);
        float rs[2][2] = {{0.f, 0.f}, {0.f, 0.f}};
        float cs[8][2];
        #pragma unroll
        for (int n = 0; n < 8; n++) { cs[n][0] = 0.f; cs[n][1] = 0.f; }

        if (!isdiag && !islab) {
            // Fast path: no per-element predicates.
            #pragma unroll
            for (int m = 0; m < 2; m++)
                #pragma unroll
                for (int n = 0; n < 8; n++)
                    #pragma unroll
                    for (int q = 0; q < 4; q++) {
                        float e = ex2f(acc[m][n][q] * SCALE_EX2);
                        rs[m][q >> 1] += e;
                        cs[n][q & 1] += e;
                    }
        } else {
            #pragma unroll
            for (int m = 0; m < 2; m++)
                #pragma unroll
                for (int n = 0; n < 8; n++)
                    #pragma unroll
                    for (int q = 0; q < 4; q++) {
                        const int rh = q >> 1, kp = q & 1;
                        const int rloc = wm * 32 + m * 16 + lr + rh * 8;
                        const int cloc = wn * 64 + n * 8 + c4 * 2 + kp;
                        float e = ex2f(acc[m][n][q] * SCALE_EX2);
                        bool dg = isdiag && (rloc == cloc);
                        if (!dg) { rs[m][rh] += e; cs[n][kp] += e; }
                        if (islab && rloc == cloc) {
                            float s = 2.0f * acc[m][n][q];
                            g_slabel[TILE * ii + rloc] = s;
                            g_slabel[TILE * jj + cloc] = s;
                        }
                    }
        }

        // Row reduce (lanes differing in bits 0-1).
        #pragma unroll
        for (int m = 0; m < 2; m++)
            #pragma unroll
            for (int rh = 0; rh < 2; rh++) {
                rs[m][rh] += __shfl_xor_sync(0xffffffffu, rs[m][rh], 1);
                rs[m][rh] += __shfl_xor_sync(0xffffffffu, rs[m][rh], 2);
            }
        if (c4 == 0) {
            #pragma unroll
            for (int m = 0; m < 2; m++)
                #pragma unroll
                for (int rh = 0; rh < 2; rh++) {
                    int grow = TILE * ii + wm * 32 + m * 16 + lr + rh * 8;
                    g_partial[(size_t)grow * NSLOT + 2 * jj + wn] = rs[m][rh];
                }
        }

        // Column reduce (bits 2-4 in-warp, wm via smem).
        #pragma unroll
        for (int n = 0; n < 8; n++)
            #pragma unroll
            for (int kp = 0; kp < 2; kp++) {
                cs[n][kp] += __shfl_xor_sync(0xffffffffu, cs[n][kp], 4);
                cs[n][kp] += __shfl_xor_sync(0xffffffffu, cs[n][kp], 8);
                cs[n][kp] += __shfl_xor_sync(0xffffffffu, cs[n][kp], 16);
            }
        if (lane < 4) {
            #pragma unroll
            for (int n = 0; n < 8; n++)
                #pragma unroll
                for (int kp = 0; kp < 2; kp++)
                    colstage[wm][wn * 64 + n * 8 + lane * 2 + kp] = cs[n][kp];
        }
        __syncthreads();
        if (!isdiag && tid < 128) {
            float v = colstage[0][tid] + colstage[1][tid]
                    + colstage[2][tid] + colstage[3][tid];
            size_t base = (size_t)(TILE * jj + tid) * NSLOT;
            g_partial[base + 2 * ii] = v;
            g_partial[base + 2 * ii + 1] = 0.f;
        }
    }
}

// ---------------- Kernel 3: per-row logsumexp + fused final reduce --------------
__global__ void finalize_kernel(float* __restrict__ out) {
    const int tid = threadIdx.x, lane = tid & 31;
    const int row = blockIdx.x * 32 + (tid >> 3);
    const float4* p = (const float4*)&g_partial[(size_t)row * NSLOT + (tid & 7) * 16];
    float4 a = p[0], b = p[1], c = p[2], d = p[3];
    float s = (a.x + a.y + a.z + a.w) + (b.x + b.y + b.z + b.w)
            + (c.x + c.y + c.z + c.w) + (d.x + d.y + d.z + d.w);
    s += __shfl_xor_sync(0xffffffffu, s, 1);
    s += __shfl_xor_sync(0xffffffffu, s, 2);
    s += __shfl_xor_sync(0xffffffffu, s, 4);
    float val = ((tid & 7) == 0) ? (logf(s) - g_slabel[row]) : 0.f;
    val += __shfl_xor_sync(0xffffffffu, val, 8);
    val += __shfl_xor_sync(0xffffffffu, val, 16);
    __shared__ float ws[8];
    __shared__ unsigned islast;
    if (lane == 0) ws[tid >> 5] = val;
    __syncthreads();
    if (tid == 0) {
        float t = 0.f;
        #pragma unroll
        for (int i = 0; i < 8; i++) t += ws[i];
        g_bsum[blockIdx.x] = t;
        __threadfence();
        unsigned tk = atomicAdd(&g_ticket, 1u);
        islast = (tk == gridDim.x - 1) ? 1u : 0u;
    }
    __syncthreads();
    if (islast) {
        // Last block: deterministic fixed-order reduce of 256 block sums.
        float v = 0.f;
        if (tid < 32) {
            #pragma unroll
            for (int i = 0; i < 8; i++) v += g_bsum[tid * 8 + i];
            #pragma unroll
            for (int o = 16; o > 0; o >>= 1) v += __shfl_xor_sync(0xffffffffu, v, o);
            if (tid == 0) {
                out[0] = v / (float)NROWS;
                g_ticket = 0;          // reset for next graph replay
            }
        }
    }
}

extern "C" void kernel_launch(void* const* d_in, const int* in_sizes, int n_in,
                              void* d_out, int out_size) {
    const float* zi = (const float*)d_in[0];
    const float* zj = (const float*)d_in[1];
    float* out = (float*)d_out;

    cudaFuncSetAttribute(simloss_kernel,
                         cudaFuncAttributeMaxDynamicSharedMemorySize, 98304);

    normalize_kernel<<<NROWS / 32, 256>>>(zi, zj);
    simloss_kernel<<<GEMM_CTAS, 256, 98304>>>();
    finalize_kernel<<<256, 256>>>(out);
}